// round 1
// baseline (speedup 1.0000x reference)
#include <cuda_runtime.h>

// Problem constants
#define BB   32
#define CI   64
#define CO   64
#define HH   128
#define WW   128
#define M1   32
#define M2   32
#define SS   64      // retained kx rows: {0..31} U {96..127}
#define WOUT 65      // rfft width = W/2+1, used as the ifft length on last axis
#define MPAD 68      // m padded to multiple of 4 for tiling (extra cols discarded)

// ---------------- scratch (device globals; no allocations allowed) ----------------
__device__ float2 g_Y[(size_t)BB * CI * HH * M2];    // stage A out: [b*CI+i][n][ky]
__device__ float2 g_X[(size_t)SS * M2 * BB * CI];    // stage B out (mode-major): [(s*32+ky)][b*64+i]
__device__ float2 g_G[(size_t)BB * CO * SS * M2];    // stage C out: [b*64+o][s][ky]
__device__ float2 g_T[(size_t)BB * CO * SS * MPAD];  // stage D out: [b*64+o][s][m]

// twiddle tables
__device__ float2 g_FW[HH * M2];    // [m][ky]  e^{-2pi i ky m /128}
__device__ float2 g_FH[SS * HH];    // [s][n]   e^{-2pi i kx(s) n /128}
__device__ float2 g_IKY[M2 * MPAD]; // [ky][m]  e^{+2pi i ky m /65}
__device__ float2 g_IKX[SS * HH];   // [s][n]   e^{+2pi i kx(s) n /128}

// ---------------- twiddle fill ----------------
__global__ void k_fill() {
    int t  = blockIdx.x * blockDim.x + threadIdx.x;
    int NT = gridDim.x * blockDim.x;
    const double P2 = 6.283185307179586476925286766559;

    for (int idx = t; idx < HH * M2; idx += NT) {
        int m = idx >> 5, ky = idx & 31;
        double a = -P2 * (double)((m * ky) & 127) / 128.0;
        g_FW[idx] = make_float2((float)cos(a), (float)sin(a));
    }
    for (int idx = t; idx < SS * HH; idx += NT) {
        int s = idx >> 7, n = idx & 127;
        int kx = (s < 32) ? s : (s + 64);   // 96..127 for s in 32..63
        double a = -P2 * (double)((kx * n) & 127) / 128.0;
        g_FH[idx]  = make_float2((float)cos(a), (float)sin(a));
        g_IKX[idx] = make_float2((float)cos(-a), (float)sin(-a));
    }
    for (int idx = t; idx < M2 * MPAD; idx += NT) {
        int ky = idx / MPAD, m = idx % MPAD;
        double a = P2 * (double)((ky * m) % 65) / 65.0;
        g_IKY[idx] = make_float2((float)cos(a), (float)sin(a));
    }
}

// ---------------- Stage A: real DFT along W (128 -> 32 freqs) ----------------
// rows = (b,i,n) flattened: 262144 rows. Block handles 32 rows, 128 threads.
#define ROWS_A 32
__global__ __launch_bounds__(128) void kA(const float* __restrict__ x) {
    __shared__ float  xs[ROWS_A][WW];   // 16 KB
    __shared__ float2 tws[WW][M2];      // 32 KB, [m][ky]
    int tid = threadIdx.x;

    for (int idx = tid; idx < WW * M2; idx += 128)
        ((float2*)tws)[idx] = g_FW[idx];

    size_t rowBase = (size_t)blockIdx.x * ROWS_A;
    const float* xp = x + rowBase * WW;
    for (int idx = tid; idx < ROWS_A * WW; idx += 128)
        ((float*)xs)[idx] = xp[idx];
    __syncthreads();

    int ky = tid & 31, rg = tid >> 5;   // rg 0..3, rows rg + 4k
    float ar[8], ai[8];
#pragma unroll
    for (int k = 0; k < 8; k++) { ar[k] = 0.f; ai[k] = 0.f; }

    for (int m = 0; m < WW; m++) {
        float2 tw = tws[m][ky];
#pragma unroll
        for (int k = 0; k < 8; k++) {
            float xv = xs[rg + 4 * k][m];
            ar[k] = fmaf(xv, tw.x, ar[k]);
            ai[k] = fmaf(xv, tw.y, ai[k]);
        }
    }
#pragma unroll
    for (int k = 0; k < 8; k++) {
        size_t row = rowBase + rg + 4 * k;
        g_Y[row * M2 + ky] = make_float2(ar[k], ai[k]);
    }
}

// ---------------- Stage B: complex DFT along H (128 -> 64 rows) ----------------
// Block per (b,i). 256 threads: ky = tid&31, sg = tid>>5 -> s = sg + 8j.
__global__ __launch_bounds__(256) void kB() {
    __shared__ float2 Ys[32][M2];   // one n-chunk: 8 KB
    __shared__ float2 Fs[SS][32];   // FH n-chunk: 16 KB
    int tid = threadIdx.x;
    int bi  = blockIdx.x;
    const float2* Yg = g_Y + (size_t)bi * HH * M2;

    int ky = tid & 31, sg = tid >> 5;
    float2 acc[8];
#pragma unroll
    for (int j = 0; j < 8; j++) acc[j] = make_float2(0.f, 0.f);

    for (int c = 0; c < 4; c++) {
        __syncthreads();
        for (int idx = tid; idx < 32 * M2; idx += 256)
            ((float2*)Ys)[idx] = Yg[c * 32 * M2 + idx];
        for (int idx = tid; idx < SS * 32; idx += 256) {
            int s = idx >> 5, nl = idx & 31;
            Fs[s][nl] = g_FH[s * HH + c * 32 + nl];
        }
        __syncthreads();

        for (int nl = 0; nl < 32; nl++) {
            float2 yv = Ys[nl][ky];
#pragma unroll
            for (int j = 0; j < 8; j++) {
                float2 tw = Fs[sg + 8 * j][nl];
                acc[j].x = fmaf(yv.x, tw.x, fmaf(-yv.y, tw.y, acc[j].x));
                acc[j].y = fmaf(yv.x, tw.y, fmaf( yv.y, tw.x, acc[j].y));
            }
        }
    }
#pragma unroll
    for (int j = 0; j < 8; j++) {
        int s = sg + 8 * j;
        g_X[((size_t)(s * 32 + ky)) * (BB * CI) + bi] = acc[j];
    }
}

// ---------------- Stage C: per-mode channel mix G = X * conj(W) ----------------
// Block per mode (s,ky). 256 threads: o = tid&63, bg = tid>>6 -> b = bg + 4k.
__global__ __launch_bounds__(256) void kC(const float* __restrict__ w1r, const float* __restrict__ w1i,
                                          const float* __restrict__ w2r, const float* __restrict__ w2i) {
    __shared__ float2 Xs[BB][CI];   // 16 KB
    __shared__ float2 Ws[CI][CO];   // 32 KB  (wr, wi)
    int tid  = threadIdx.x;
    int mode = blockIdx.x;
    int s = mode >> 5, ky = mode & 31;

    const float2* Xg = g_X + (size_t)mode * (BB * CI);
    for (int idx = tid; idx < BB * CI; idx += 256)
        ((float2*)Xs)[idx] = Xg[idx];

    const float* wr = (s < 32) ? w1r : w2r;
    const float* wi = (s < 32) ? w1i : w2i;
    int sm = s & 31;
    for (int idx = tid; idx < CI * CO; idx += 256) {
        size_t g = ((size_t)idx * M1 + sm) * M2 + ky;
        ((float2*)Ws)[idx] = make_float2(wr[g], wi[g]);
    }
    __syncthreads();

    int o = tid & 63, bg = tid >> 6;
    float2 acc[8];
#pragma unroll
    for (int k = 0; k < 8; k++) acc[k] = make_float2(0.f, 0.f);

    for (int i = 0; i < CI; i++) {
        float2 wv = Ws[i][o];
#pragma unroll
        for (int k = 0; k < 8; k++) {
            float2 xv = Xs[bg + 4 * k][i];
            // G += X * conj(W):  Gr += Xr*wr + Xi*wi ; Gi += Xi*wr - Xr*wi
            acc[k].x = fmaf(xv.x, wv.x, fmaf( xv.y, wv.y, acc[k].x));
            acc[k].y = fmaf(xv.y, wv.x, fmaf(-xv.x, wv.y, acc[k].y));
        }
    }
#pragma unroll
    for (int k = 0; k < 8; k++) {
        int b = bg + 4 * k;
        g_G[(((size_t)(b * CO + o)) * SS + s) * M2 + ky] = acc[k];
    }
}

// ---------------- Stage D: inverse length-65 DFT along ky (32 -> 68 padded) ----------------
// Block per (b,o). 272 threads: m = tid%68, sg = tid/68 -> s = sg + 4j.
__global__ __launch_bounds__(272) void kD() {
    __shared__ float2 Gs[SS][M2];     // 16 KB
    __shared__ float2 Ks[M2][MPAD];   // 17 KB, [ky][m]
    int tid = threadIdx.x;
    int bo  = blockIdx.x;

    const float2* Gg = g_G + (size_t)bo * SS * M2;
    for (int idx = tid; idx < SS * M2; idx += 272)
        ((float2*)Gs)[idx] = Gg[idx];
    for (int idx = tid; idx < M2 * MPAD; idx += 272)
        ((float2*)Ks)[idx] = g_IKY[idx];
    __syncthreads();

    int m = tid % MPAD, sg = tid / MPAD;   // sg 0..3
    float2 acc[16];
#pragma unroll
    for (int j = 0; j < 16; j++) acc[j] = make_float2(0.f, 0.f);

    for (int ky = 0; ky < M2; ky++) {
        float2 e = Ks[ky][m];
#pragma unroll
        for (int j = 0; j < 16; j++) {
            float2 g = Gs[sg + 4 * j][ky];
            acc[j].x = fmaf(g.x, e.x, fmaf(-g.y, e.y, acc[j].x));
            acc[j].y = fmaf(g.x, e.y, fmaf( g.y, e.x, acc[j].y));
        }
    }
    float2* Tp = g_T + (size_t)bo * SS * MPAD;
#pragma unroll
    for (int j = 0; j < 16; j++)
        Tp[(sg + 4 * j) * MPAD + m] = acc[j];
}

// ---------------- Stage E: inverse DFT along kx + real part + scale ----------------
// Block per (b,o). 272 threads: m = tid%68, ng = tid/68 -> n = ng + 4j (j 0..31).
__global__ __launch_bounds__(272) void kE(float* __restrict__ out) {
    __shared__ float2 Ts[16][MPAD];   // s-chunk of T: ~8.7 KB
    __shared__ float2 Es[16][HH];     // IKX chunk [s][n]: 16 KB
    int tid = threadIdx.x;
    int bo  = blockIdx.x;
    int m = tid % MPAD, ng = tid / MPAD;

    float acc[32];
#pragma unroll
    for (int j = 0; j < 32; j++) acc[j] = 0.f;

    const float2* Tg = g_T + (size_t)bo * SS * MPAD;
    for (int c = 0; c < 4; c++) {
        __syncthreads();
        for (int idx = tid; idx < 16 * MPAD; idx += 272)
            ((float2*)Ts)[idx] = Tg[c * 16 * MPAD + idx];
        for (int idx = tid; idx < 16 * HH; idx += 272) {
            int sl = idx >> 7, n = idx & 127;
            Es[sl][n] = g_IKX[(c * 16 + sl) * HH + n];
        }
        __syncthreads();

        for (int sl = 0; sl < 16; sl++) {
            float2 tv = Ts[sl][m];
#pragma unroll
            for (int j = 0; j < 32; j++) {
                float2 e = Es[sl][ng + 4 * j];
                // Re(T * e^{i th}) = Tr*c - Ti*s
                acc[j] = fmaf(tv.x, e.x, fmaf(-tv.y, e.y, acc[j]));
            }
        }
    }

    if (m < WOUT) {
        float* op = out + (size_t)bo * HH * WOUT;
        const float sc = 1.0f / (128.0f * 65.0f);
#pragma unroll
        for (int j = 0; j < 32; j++) {
            int n = ng + 4 * j;
            op[(size_t)n * WOUT + m] = acc[j] * sc;
        }
    }
}

// ---------------- launch ----------------
extern "C" void kernel_launch(void* const* d_in, const int* in_sizes, int n_in,
                              void* d_out, int out_size) {
    (void)in_sizes; (void)n_in; (void)out_size;
    const float* x   = (const float*)d_in[0];
    const float* w1r = (const float*)d_in[1];
    const float* w1i = (const float*)d_in[2];
    const float* w2r = (const float*)d_in[3];
    const float* w2i = (const float*)d_in[4];
    float* out = (float*)d_out;

    k_fill<<<32, 256>>>();
    kA<<<(BB * CI * HH) / ROWS_A, 128>>>(x);        // 8192 blocks
    kB<<<BB * CI, 256>>>();                          // 2048 blocks
    kC<<<SS * M2, 256>>>(w1r, w1i, w2r, w2i);        // 2048 blocks (modes)
    kD<<<BB * CO, 272>>>();                          // 2048 blocks
    kE<<<BB * CO, 272>>>(out);                       // 2048 blocks
}

// round 2
// speedup vs baseline: 1.0627x; 1.0627x over previous
#include <cuda_runtime.h>

// Problem constants
#define BB   32
#define CI   64
#define CO   64
#define HH   128
#define WW   128
#define M1   32
#define M2   32
#define SS   64      // retained kx rows: {0..31} U {96..127}
#define WOUT 65      // rfft width = W/2+1 = ifft length on last axis
#define MPAD 68      // m padded for tiling (extra cols discarded)

// ---------------- scratch (device globals) ----------------
__device__ float2 g_Y[(size_t)BB * CI * HH * M2];    // stage A out: [bi][n][ky]
__device__ float2 g_X[(size_t)SS * M2 * BB * CI];    // stage B out: [mode][b*64+i]
__device__ float2 g_G[(size_t)SS * M2 * BB * CO];    // stage C out (mode-major): [mode][b*64+o]
__device__ float2 g_T[(size_t)BB * CO * SS * MPAD];  // stage D out: [bo][s][m]

// twiddle tables
__device__ float2 g_FA[M2 * M2];     // [n1][ky]  e^{-2pi i ky n1/128}   (32x32)
__device__ float2 g_FB[SS * 32];     // [s][n1]   e^{-2pi i kx(s) n1/128}
__device__ float2 g_E2[SS * 32];     // [s][n1]   e^{+2pi i kx(s) n1/128}
__device__ float2 g_IKY[M2 * MPAD];  // [ky][m]   e^{+2pi i ky m/65}

// ---------------- twiddle fill ----------------
__global__ void k_fill() {
    int t  = blockIdx.x * blockDim.x + threadIdx.x;
    int NT = gridDim.x * blockDim.x;
    const double P2 = 6.283185307179586476925286766559;

    for (int idx = t; idx < M2 * M2; idx += NT) {
        int n1 = idx >> 5, ky = idx & 31;
        double a = -P2 * (double)((ky * n1) & 127) / 128.0;
        g_FA[idx] = make_float2((float)cos(a), (float)sin(a));
    }
    for (int idx = t; idx < SS * 32; idx += NT) {
        int s = idx >> 5, n1 = idx & 31;
        int kx = (s < 32) ? s : (s + 64);
        double a = -P2 * (double)((kx * n1) & 127) / 128.0;
        float c = (float)cos(a), sn = (float)sin(a);
        g_FB[idx] = make_float2(c, sn);
        g_E2[idx] = make_float2(c, -sn);
    }
    for (int idx = t; idx < M2 * MPAD; idx += NT) {
        int ky = idx / MPAD, m = idx % MPAD;
        double a = P2 * (double)((ky * m) % 65) / 65.0;
        g_IKY[idx] = make_float2((float)cos(a), (float)sin(a));
    }
}

// ---------------- Stage A: real DFT along W (128 -> 32), radix-4 folded ----------------
// Per row: y_r[n1] = sum_{n2} x[n1+32n2] (-i)^{r n2}  (adds only), then
// X[ky] = sum_{n1<32} y_{ky&3}[n1] e^{-2pi i ky n1/128}.
// Block: 32 rows, 256 threads. Thread: ky = tid&31, rows rg+8j (j<4).
__global__ __launch_bounds__(256, 5) void kA(const float* __restrict__ x) {
    __shared__ float2 ys[32][4][33];   // [row][class][n1] (pad 33 -> class offsets hit distinct banks)
    __shared__ float2 tws[32][32];     // [n1][ky] 8 KB
    int tid = threadIdx.x;

    for (int idx = tid; idx < 32 * 32; idx += 256)
        ((float2*)tws)[idx] = g_FA[idx];

    size_t rowBase = (size_t)blockIdx.x * 32;
    // phase 1: radix-4 fold straight from global (coalesced)
#pragma unroll
    for (int it = 0; it < 4; it++) {
        int idx = tid + 256 * it;
        int row = idx >> 5, n1 = idx & 31;
        const float* xp = x + (rowBase + row) * WW;
        float x0 = xp[n1], x1 = xp[n1 + 32], x2 = xp[n1 + 64], x3 = xp[n1 + 96];
        float p = x0 + x2, q = x0 - x2, u = x1 + x3, v = x3 - x1;
        ys[row][0][n1] = make_float2(p + u, 0.f);
        ys[row][2][n1] = make_float2(p - u, 0.f);
        ys[row][1][n1] = make_float2(q,  v);   // y1 = (x0-x2) - i(x1-x3)
        ys[row][3][n1] = make_float2(q, -v);
    }
    __syncthreads();

    int ky = tid & 31, rg = tid >> 5;
    int cls = ky & 3;
    float2 acc[4];
#pragma unroll
    for (int j = 0; j < 4; j++) acc[j] = make_float2(0.f, 0.f);

    for (int n1 = 0; n1 < 32; n1++) {
        float2 tw = tws[n1][ky];
#pragma unroll
        for (int j = 0; j < 4; j++) {
            float2 y = ys[rg + 8 * j][cls][n1];
            acc[j].x = fmaf(y.x, tw.x, fmaf(-y.y, tw.y, acc[j].x));
            acc[j].y = fmaf(y.x, tw.y, fmaf( y.y, tw.x, acc[j].y));
        }
    }
#pragma unroll
    for (int j = 0; j < 4; j++)
        g_Y[(rowBase + rg + 8 * j) * M2 + ky] = acc[j];
}

// ---------------- Stage B: complex DFT along H (128 -> 64), radix-4 folded ----------------
// Block per (b,i). 256 threads: ky = tid&31, sg = tid>>5 -> s = sg+8j, class = sg&3.
__global__ __launch_bounds__(256, 4) void kB() {
    __shared__ float2 ys[4][32][32];   // [class][n1][ky] 32 KB
    __shared__ float2 tws[SS][32];     // [s][n1] 16 KB
    int tid = threadIdx.x;
    int bi  = blockIdx.x;
    const float2* Yg = g_Y + (size_t)bi * HH * M2;

    for (int idx = tid; idx < SS * 32; idx += 256)
        ((float2*)tws)[idx] = g_FB[idx];

    // phase 1: radix-4 fold (complex), coalesced loads
#pragma unroll
    for (int it = 0; it < 4; it++) {
        int idx = tid + 256 * it;
        int n1 = idx >> 5, ky = idx & 31;
        float2 Y0 = Yg[n1 * 32 + ky];
        float2 Y1 = Yg[(n1 + 32) * 32 + ky];
        float2 Y2 = Yg[(n1 + 64) * 32 + ky];
        float2 Y3 = Yg[(n1 + 96) * 32 + ky];
        float2 a = make_float2(Y0.x + Y2.x, Y0.y + Y2.y);
        float2 b = make_float2(Y0.x - Y2.x, Y0.y - Y2.y);
        float2 c = make_float2(Y1.x + Y3.x, Y1.y + Y3.y);
        float2 d = make_float2(Y1.x - Y3.x, Y1.y - Y3.y);
        ys[0][n1][ky] = make_float2(a.x + c.x, a.y + c.y);
        ys[2][n1][ky] = make_float2(a.x - c.x, a.y - c.y);
        ys[1][n1][ky] = make_float2(b.x + d.y, b.y - d.x);   // b - i d
        ys[3][n1][ky] = make_float2(b.x - d.y, b.y + d.x);   // b + i d
    }
    __syncthreads();

    int ky = tid & 31, sg = tid >> 5;
    int cls = sg & 3;
    float2 acc[8];
#pragma unroll
    for (int j = 0; j < 8; j++) acc[j] = make_float2(0.f, 0.f);

    for (int n1 = 0; n1 < 32; n1++) {
        float2 y = ys[cls][n1][ky];
#pragma unroll
        for (int j = 0; j < 8; j++) {
            float2 tw = tws[sg + 8 * j][n1];
            acc[j].x = fmaf(y.x, tw.x, fmaf(-y.y, tw.y, acc[j].x));
            acc[j].y = fmaf(y.x, tw.y, fmaf( y.y, tw.x, acc[j].y));
        }
    }
#pragma unroll
    for (int j = 0; j < 8; j++) {
        int s = sg + 8 * j;
        g_X[((size_t)(s * 32 + ky)) * (BB * CI) + bi] = acc[j];
    }
}

// ---------------- Stage C: per-mode channel mix G = X * conj(W) ----------------
// Block per mode. 128 threads: o = tid&31 (o, o+32), bg = tid>>5 -> b = bg+4k (8 b).
// 16 complex accumulators -> 64 FMA per 10 LDS. i chunked by 32 for smem.
__global__ __launch_bounds__(128, 7) void kC(const float* __restrict__ w1r, const float* __restrict__ w1i,
                                             const float* __restrict__ w2r, const float* __restrict__ w2i) {
    __shared__ float2 Xs[BB][32];   // [b][i_local] 8 KB
    __shared__ float2 Ws[32][CO];   // [i_local][o] 16 KB
    int tid  = threadIdx.x;
    int mode = blockIdx.x;
    int s = mode >> 5, ky = mode & 31;

    const float2* Xg = g_X + (size_t)mode * (BB * CI);
    const float* wr = (s < 32) ? w1r : w2r;
    const float* wi = (s < 32) ? w1i : w2i;
    int sm = s & 31;

    int o = tid & 31, bg = tid >> 5;
    float2 acc[16];
#pragma unroll
    for (int k = 0; k < 16; k++) acc[k] = make_float2(0.f, 0.f);

    for (int c = 0; c < 2; c++) {
        __syncthreads();
        for (int idx = tid; idx < BB * 32; idx += 128) {
            int b = idx >> 5, il = idx & 31;
            Xs[b][il] = Xg[b * CI + c * 32 + il];
        }
        for (int idx = tid; idx < 32 * CO; idx += 128) {
            int il = idx >> 6, o_ = idx & 63;
            int ig = c * 32 + il;
            size_t g = ((size_t)(ig * CO + o_) * M1 + sm) * M2 + ky;
            Ws[il][o_] = make_float2(wr[g], wi[g]);
        }
        __syncthreads();

        for (int il = 0; il < 32; il++) {
            float2 w0 = Ws[il][o];
            float2 w1 = Ws[il][o + 32];
#pragma unroll
            for (int k = 0; k < 8; k++) {
                float2 xv = Xs[bg + 4 * k][il];
                // G += X * conj(W)
                acc[k].x      = fmaf(xv.x, w0.x, fmaf( xv.y, w0.y, acc[k].x));
                acc[k].y      = fmaf(xv.y, w0.x, fmaf(-xv.x, w0.y, acc[k].y));
                acc[k + 8].x  = fmaf(xv.x, w1.x, fmaf( xv.y, w1.y, acc[k + 8].x));
                acc[k + 8].y  = fmaf(xv.y, w1.x, fmaf(-xv.x, w1.y, acc[k + 8].y));
            }
        }
    }
    // mode-major output -> coalesced writes (lane o consecutive)
    float2* Gp = g_G + (size_t)mode * (BB * CO);
#pragma unroll
    for (int k = 0; k < 8; k++) {
        int b = bg + 4 * k;
        Gp[b * CO + o]      = acc[k];
        Gp[b * CO + o + 32] = acc[k + 8];
    }
}

// ---------------- Stage D: inverse length-65 DFT along ky (32 -> 68 padded) ----------------
// Block per (b,o). 272 threads: m = tid%68, sg = tid/68 -> s = sg + 4j (16 s).
__global__ __launch_bounds__(272, 4) void kD() {
    __shared__ float2 Gs[SS][M2];     // 16 KB
    __shared__ float2 Ks[M2][MPAD];   // 17 KB
    int tid = threadIdx.x;
    int bo  = blockIdx.x;

    for (int idx = tid; idx < SS * M2; idx += 272)
        ((float2*)Gs)[idx] = g_G[(size_t)idx * (BB * CO) + bo];
    for (int idx = tid; idx < M2 * MPAD; idx += 272)
        ((float2*)Ks)[idx] = g_IKY[idx];
    __syncthreads();

    int m = tid % MPAD, sg = tid / MPAD;
    float2 acc[16];
#pragma unroll
    for (int j = 0; j < 16; j++) acc[j] = make_float2(0.f, 0.f);

    for (int ky = 0; ky < M2; ky++) {
        float2 e = Ks[ky][m];
#pragma unroll
        for (int j = 0; j < 16; j++) {
            float2 g = Gs[sg + 4 * j][ky];
            acc[j].x = fmaf(g.x, e.x, fmaf(-g.y, e.y, acc[j].x));
            acc[j].y = fmaf(g.x, e.y, fmaf( g.y, e.x, acc[j].y));
        }
    }
    float2* Tp = g_T + (size_t)bo * SS * MPAD;
#pragma unroll
    for (int j = 0; j < 16; j++)
        Tp[(sg + 4 * j) * MPAD + m] = acc[j];
}

// ---------------- Stage E: inverse DFT along kx, radix-4 grouped, real part ----------------
// Per (b,o), m: A_r[n1] = sum_{s: s&3==r} T[s][m] e^{+2pi i kx_s n1/128};
// out[32q+n1][m] = Re( sum_r i^{rq} A_r[n1] ) / (128*65).
// 544 threads: m = tid%68, ng = tid/68 -> n1 = ng+8j (4 n1) x 4 classes = 32-float acc.
__global__ __launch_bounds__(544, 2) void kE(float* __restrict__ out) {
    __shared__ float2 Ts[32][MPAD];   // s-chunk ~17.4 KB
    __shared__ float2 Es[SS][32];     // [s][n1] 16 KB
    int tid = threadIdx.x;
    int bo  = blockIdx.x;
    int m = tid % MPAD, ng = tid / MPAD;

    for (int idx = tid; idx < SS * 32; idx += 544)
        ((float2*)Es)[idx] = g_E2[idx];

    float2 A[4][4];   // [r][j]
#pragma unroll
    for (int r = 0; r < 4; r++)
#pragma unroll
        for (int j = 0; j < 4; j++) A[r][j] = make_float2(0.f, 0.f);

    const float2* Tg = g_T + (size_t)bo * SS * MPAD;
    for (int c = 0; c < 2; c++) {
        __syncthreads();
        for (int idx = tid; idx < 32 * MPAD; idx += 544)
            ((float2*)Ts)[idx] = Tg[c * 32 * MPAD + idx];
        __syncthreads();

        for (int t = 0; t < 8; t++) {
#pragma unroll
            for (int r = 0; r < 4; r++) {
                int sl = 4 * t + r;             // local s in chunk; global s = c*32 + sl, class = s&3 = r
                float2 tv = Ts[sl][m];
#pragma unroll
                for (int j = 0; j < 4; j++) {
                    float2 e = Es[c * 32 + sl][ng + 8 * j];
                    A[r][j].x = fmaf(tv.x, e.x, fmaf(-tv.y, e.y, A[r][j].x));
                    A[r][j].y = fmaf(tv.x, e.y, fmaf( tv.y, e.x, A[r][j].y));
                }
            }
        }
    }

    if (m < WOUT) {
        float* op = out + (size_t)bo * HH * WOUT;
        const float sc = 1.0f / (128.0f * 65.0f);
#pragma unroll
        for (int j = 0; j < 4; j++) {
            int n1 = ng + 8 * j;
            float a0x = A[0][j].x, a1x = A[1][j].x, a2x = A[2][j].x, a3x = A[3][j].x;
            float a1y = A[1][j].y, a3y = A[3][j].y;
            float v0 = a0x + a1x + a2x + a3x;            // q=0
            float v1 = a0x - a1y - a2x + a3y;            // q=1
            float v2 = a0x - a1x + a2x - a3x;            // q=2
            float v3 = a0x + a1y - a2x - a3y;            // q=3
            op[(size_t)(n1      ) * WOUT + m] = v0 * sc;
            op[(size_t)(n1 + 32 ) * WOUT + m] = v1 * sc;
            op[(size_t)(n1 + 64 ) * WOUT + m] = v2 * sc;
            op[(size_t)(n1 + 96 ) * WOUT + m] = v3 * sc;
        }
    }
}

// ---------------- launch ----------------
extern "C" void kernel_launch(void* const* d_in, const int* in_sizes, int n_in,
                              void* d_out, int out_size) {
    (void)in_sizes; (void)n_in; (void)out_size;
    const float* x   = (const float*)d_in[0];
    const float* w1r = (const float*)d_in[1];
    const float* w1i = (const float*)d_in[2];
    const float* w2r = (const float*)d_in[3];
    const float* w2i = (const float*)d_in[4];
    float* out = (float*)d_out;

    k_fill<<<32, 256>>>();
    kA<<<(BB * CI * HH) / 32, 256>>>(x);            // 8192 blocks
    kB<<<BB * CI, 256>>>();                          // 2048 blocks
    kC<<<SS * M2, 128>>>(w1r, w1i, w2r, w2i);        // 2048 blocks
    kD<<<BB * CO, 272>>>();                          // 2048 blocks
    kE<<<BB * CO, 544>>>(out);                       // 2048 blocks
}

// round 3
// speedup vs baseline: 1.7355x; 1.6331x over previous
#include <cuda_runtime.h>

// Problem constants
#define BB   32
#define CI   64
#define CO   64
#define HH   128
#define WW   128
#define M1   32
#define M2   32
#define SS   64      // retained kx rows: {0..31} U {96..127}
#define WOUT 65      // rfft width = W/2+1 = ifft length on last axis
#define MPAD 68      // m padded for tiling (extra cols discarded)

// ---------------- scratch (device globals) ----------------
__device__ float2 g_Y[(size_t)BB * CI * HH * M2];    // stage A out: [bi][n][ky]
__device__ float2 g_X[(size_t)SS * M2 * BB * CI];    // stage B out: [mode][b*64+i]
__device__ float2 g_G[(size_t)SS * M2 * BB * CO];    // stage C out (mode-major): [mode][b*64+o]
__device__ float2 g_T[(size_t)BB * CO * SS * MPAD];  // stage D out: [bo][s][m]
__device__ float2 g_W[(size_t)SS * M2 * CI * CO];    // transposed weights: [mode][i][o]

// twiddle tables
__device__ float2 g_FA[M2 * M2];     // [n1][ky]  e^{-2pi i ky n1/128}
__device__ float2 g_FB[SS * 32];     // [s][n1]   e^{-2pi i kx(s) n1/128}
__device__ float2 g_E2[SS * 32];     // [s][n1]   e^{+2pi i kx(s) n1/128}
__device__ float2 g_IKY[M2 * MPAD];  // [ky][m]   e^{+2pi i ky m/65}

// ---------------- twiddle fill ----------------
__global__ void k_fill() {
    int t  = blockIdx.x * blockDim.x + threadIdx.x;
    int NT = gridDim.x * blockDim.x;
    const double P2 = 6.283185307179586476925286766559;

    for (int idx = t; idx < M2 * M2; idx += NT) {
        int n1 = idx >> 5, ky = idx & 31;
        double a = -P2 * (double)((ky * n1) & 127) / 128.0;
        g_FA[idx] = make_float2((float)cos(a), (float)sin(a));
    }
    for (int idx = t; idx < SS * 32; idx += NT) {
        int s = idx >> 5, n1 = idx & 31;
        int kx = (s < 32) ? s : (s + 64);
        double a = -P2 * (double)((kx * n1) & 127) / 128.0;
        float c = (float)cos(a), sn = (float)sin(a);
        g_FB[idx] = make_float2(c, sn);
        g_E2[idx] = make_float2(c, -sn);
    }
    for (int idx = t; idx < M2 * MPAD; idx += NT) {
        int ky = idx / MPAD, m = idx % MPAD;
        double a = P2 * (double)((ky * m) % 65) / 65.0;
        g_IKY[idx] = make_float2((float)cos(a), (float)sin(a));
    }
}

// ---------------- kW: weight transpose -> g_W[mode][i][o] ----------------
// Block per (s,i): 4096 blocks, 256 threads. Read coalesced along ky (contiguous
// in source), write coalesced along o.
__global__ __launch_bounds__(256) void kW(const float* __restrict__ w1r, const float* __restrict__ w1i,
                                          const float* __restrict__ w2r, const float* __restrict__ w2i) {
    __shared__ float2 tile[CO][33];   // [o][ky], pad 33 -> write-phase reads 2-way conflict max
    int tid = threadIdx.x;
    int s = blockIdx.x >> 6, i = blockIdx.x & 63;
    const float* wr = (s < 32) ? w1r : w2r;
    const float* wi = (s < 32) ? w1i : w2i;
    int sm = s & 31;

    // read: lanes along ky -> 128B coalesced per o
    for (int idx = tid; idx < CO * M2; idx += 256) {
        int o = idx >> 5, ky = idx & 31;
        size_t g = ((size_t)(i * CO + o) * M1 + sm) * M2 + ky;
        tile[o][ky] = make_float2(wr[g], wi[g]);
    }
    __syncthreads();
    // write: lanes along o -> 512B coalesced per ky
    for (int idx = tid; idx < M2 * CO; idx += 256) {
        int ky = idx >> 6, o = idx & 63;
        g_W[((size_t)(s * 32 + ky) * CI + i) * CO + o] = tile[o][ky];
    }
}

// ---------------- Stage A: real DFT along W (128 -> 32), radix-4 folded ----------------
__global__ __launch_bounds__(256, 5) void kA(const float* __restrict__ x) {
    __shared__ float2 ys[32][4][33];   // [row][class][n1]
    __shared__ float2 tws[32][32];     // [n1][ky] 8 KB
    int tid = threadIdx.x;

    for (int idx = tid; idx < 32 * 32; idx += 256)
        ((float2*)tws)[idx] = g_FA[idx];

    size_t rowBase = (size_t)blockIdx.x * 32;
#pragma unroll
    for (int it = 0; it < 4; it++) {
        int idx = tid + 256 * it;
        int row = idx >> 5, n1 = idx & 31;
        const float* xp = x + (rowBase + row) * WW;
        float x0 = xp[n1], x1 = xp[n1 + 32], x2 = xp[n1 + 64], x3 = xp[n1 + 96];
        float p = x0 + x2, q = x0 - x2, u = x1 + x3, v = x3 - x1;
        ys[row][0][n1] = make_float2(p + u, 0.f);
        ys[row][2][n1] = make_float2(p - u, 0.f);
        ys[row][1][n1] = make_float2(q,  v);
        ys[row][3][n1] = make_float2(q, -v);
    }
    __syncthreads();

    int ky = tid & 31, rg = tid >> 5;
    int cls = ky & 3;
    float2 acc[4];
#pragma unroll
    for (int j = 0; j < 4; j++) acc[j] = make_float2(0.f, 0.f);

    for (int n1 = 0; n1 < 32; n1++) {
        float2 tw = tws[n1][ky];
#pragma unroll
        for (int j = 0; j < 4; j++) {
            float2 y = ys[rg + 8 * j][cls][n1];
            acc[j].x = fmaf(y.x, tw.x, fmaf(-y.y, tw.y, acc[j].x));
            acc[j].y = fmaf(y.x, tw.y, fmaf( y.y, tw.x, acc[j].y));
        }
    }
#pragma unroll
    for (int j = 0; j < 4; j++)
        g_Y[(rowBase + rg + 8 * j) * M2 + ky] = acc[j];
}

// ---------------- Stage B: complex DFT along H (128 -> 64), radix-4 folded ----------------
__global__ __launch_bounds__(256, 4) void kB() {
    __shared__ float2 ys[4][32][32];   // [class][n1][ky] 32 KB
    __shared__ float2 tws[SS][32];     // [s][n1] 16 KB
    int tid = threadIdx.x;
    int bi  = blockIdx.x;
    const float2* Yg = g_Y + (size_t)bi * HH * M2;

    for (int idx = tid; idx < SS * 32; idx += 256)
        ((float2*)tws)[idx] = g_FB[idx];

#pragma unroll
    for (int it = 0; it < 4; it++) {
        int idx = tid + 256 * it;
        int n1 = idx >> 5, ky = idx & 31;
        float2 Y0 = Yg[n1 * 32 + ky];
        float2 Y1 = Yg[(n1 + 32) * 32 + ky];
        float2 Y2 = Yg[(n1 + 64) * 32 + ky];
        float2 Y3 = Yg[(n1 + 96) * 32 + ky];
        float2 a = make_float2(Y0.x + Y2.x, Y0.y + Y2.y);
        float2 b = make_float2(Y0.x - Y2.x, Y0.y - Y2.y);
        float2 c = make_float2(Y1.x + Y3.x, Y1.y + Y3.y);
        float2 d = make_float2(Y1.x - Y3.x, Y1.y - Y3.y);
        ys[0][n1][ky] = make_float2(a.x + c.x, a.y + c.y);
        ys[2][n1][ky] = make_float2(a.x - c.x, a.y - c.y);
        ys[1][n1][ky] = make_float2(b.x + d.y, b.y - d.x);
        ys[3][n1][ky] = make_float2(b.x - d.y, b.y + d.x);
    }
    __syncthreads();

    int ky = tid & 31, sg = tid >> 5;
    int cls = sg & 3;
    float2 acc[8];
#pragma unroll
    for (int j = 0; j < 8; j++) acc[j] = make_float2(0.f, 0.f);

    for (int n1 = 0; n1 < 32; n1++) {
        float2 y = ys[cls][n1][ky];
#pragma unroll
        for (int j = 0; j < 8; j++) {
            float2 tw = tws[sg + 8 * j][n1];
            acc[j].x = fmaf(y.x, tw.x, fmaf(-y.y, tw.y, acc[j].x));
            acc[j].y = fmaf(y.x, tw.y, fmaf( y.y, tw.x, acc[j].y));
        }
    }
#pragma unroll
    for (int j = 0; j < 8; j++) {
        int s = sg + 8 * j;
        g_X[((size_t)(s * 32 + ky)) * (BB * CI) + bi] = acc[j];
    }
}

// ---------------- Stage C: per-mode channel mix G = X * conj(W) ----------------
// Block per mode. 128 threads: o = tid&31 (o, o+32), bg = tid>>5 -> b = bg+4k.
// Weights now read CONTIGUOUSLY from g_W[mode][i][o].
__global__ __launch_bounds__(128, 7) void kC() {
    __shared__ float2 Xs[BB][32];   // [b][i_local] 8 KB
    __shared__ float2 Ws[32][CO];   // [i_local][o] 16 KB
    int tid  = threadIdx.x;
    int mode = blockIdx.x;

    const float2* Xg = g_X + (size_t)mode * (BB * CI);
    const float2* Wg = g_W + (size_t)mode * (CI * CO);

    int o = tid & 31, bg = tid >> 5;
    float2 acc[16];
#pragma unroll
    for (int k = 0; k < 16; k++) acc[k] = make_float2(0.f, 0.f);

    for (int c = 0; c < 2; c++) {
        __syncthreads();
        for (int idx = tid; idx < BB * 32; idx += 128) {
            int b = idx >> 5, il = idx & 31;
            Xs[b][il] = Xg[b * CI + c * 32 + il];
        }
        for (int idx = tid; idx < 32 * CO; idx += 128)
            ((float2*)Ws)[idx] = Wg[c * 32 * CO + idx];   // contiguous, coalesced
        __syncthreads();

        for (int il = 0; il < 32; il++) {
            float2 w0 = Ws[il][o];
            float2 w1 = Ws[il][o + 32];
#pragma unroll
            for (int k = 0; k < 8; k++) {
                float2 xv = Xs[bg + 4 * k][il];
                acc[k].x      = fmaf(xv.x, w0.x, fmaf( xv.y, w0.y, acc[k].x));
                acc[k].y      = fmaf(xv.y, w0.x, fmaf(-xv.x, w0.y, acc[k].y));
                acc[k + 8].x  = fmaf(xv.x, w1.x, fmaf( xv.y, w1.y, acc[k + 8].x));
                acc[k + 8].y  = fmaf(xv.y, w1.x, fmaf(-xv.x, w1.y, acc[k + 8].y));
            }
        }
    }
    float2* Gp = g_G + (size_t)mode * (BB * CO);
#pragma unroll
    for (int k = 0; k < 8; k++) {
        int b = bg + 4 * k;
        Gp[b * CO + o]      = acc[k];
        Gp[b * CO + o + 32] = acc[k + 8];
    }
}

// ---------------- Stage D: inverse length-65 DFT along ky (32 -> 68) ----------------
// Block per (s, bo-chunk of 32): reads g_G coalesced along bo (mode-major),
// writes g_T in contiguous 544B rows. 272 threads: m = tid%68, bg = tid/68.
__global__ __launch_bounds__(272, 4) void kD() {
    __shared__ float2 Gs[M2][33];     // [ky][bo_local] ~8.4 KB
    __shared__ float2 Ks[M2][MPAD];   // 17.4 KB
    int tid = threadIdx.x;
    int s  = blockIdx.x >> 6;
    int cb = blockIdx.x & 63;         // bo chunk
    int bo0 = cb * 32;

    for (int idx = tid; idx < M2 * 32; idx += 272) {
        int ky = idx >> 5, bol = idx & 31;
        Gs[ky][bol] = g_G[(size_t)(s * 32 + ky) * (BB * CO) + bo0 + bol];
    }
    for (int idx = tid; idx < M2 * MPAD; idx += 272)
        ((float2*)Ks)[idx] = g_IKY[idx];
    __syncthreads();

    int m = tid % MPAD, bg = tid / MPAD;   // bg 0..3
    float2 acc[8];
#pragma unroll
    for (int j = 0; j < 8; j++) acc[j] = make_float2(0.f, 0.f);

    for (int ky = 0; ky < M2; ky++) {
        float2 e = Ks[ky][m];
#pragma unroll
        for (int j = 0; j < 8; j++) {
            float2 g = Gs[ky][bg + 4 * j];
            acc[j].x = fmaf(g.x, e.x, fmaf(-g.y, e.y, acc[j].x));
            acc[j].y = fmaf(g.x, e.y, fmaf( g.y, e.x, acc[j].y));
        }
    }
#pragma unroll
    for (int j = 0; j < 8; j++) {
        int bo = bo0 + bg + 4 * j;
        g_T[((size_t)bo * SS + s) * MPAD + m] = acc[j];
    }
}

// ---------------- Stage E: inverse DFT along kx, radix-4 grouped, real part ----------------
__global__ __launch_bounds__(544, 2) void kE(float* __restrict__ out) {
    __shared__ float2 Ts[32][MPAD];   // ~17.4 KB
    __shared__ float2 Es[SS][32];     // 16 KB
    int tid = threadIdx.x;
    int bo  = blockIdx.x;
    int m = tid % MPAD, ng = tid / MPAD;

    for (int idx = tid; idx < SS * 32; idx += 544)
        ((float2*)Es)[idx] = g_E2[idx];

    float2 A[4][4];
#pragma unroll
    for (int r = 0; r < 4; r++)
#pragma unroll
        for (int j = 0; j < 4; j++) A[r][j] = make_float2(0.f, 0.f);

    const float2* Tg = g_T + (size_t)bo * SS * MPAD;
    for (int c = 0; c < 2; c++) {
        __syncthreads();
        for (int idx = tid; idx < 32 * MPAD; idx += 544)
            ((float2*)Ts)[idx] = Tg[c * 32 * MPAD + idx];
        __syncthreads();

        for (int t = 0; t < 8; t++) {
#pragma unroll
            for (int r = 0; r < 4; r++) {
                int sl = 4 * t + r;
                float2 tv = Ts[sl][m];
#pragma unroll
                for (int j = 0; j < 4; j++) {
                    float2 e = Es[c * 32 + sl][ng + 8 * j];
                    A[r][j].x = fmaf(tv.x, e.x, fmaf(-tv.y, e.y, A[r][j].x));
                    A[r][j].y = fmaf(tv.x, e.y, fmaf( tv.y, e.x, A[r][j].y));
                }
            }
        }
    }

    if (m < WOUT) {
        float* op = out + (size_t)bo * HH * WOUT;
        const float sc = 1.0f / (128.0f * 65.0f);
#pragma unroll
        for (int j = 0; j < 4; j++) {
            int n1 = ng + 8 * j;
            float a0x = A[0][j].x, a1x = A[1][j].x, a2x = A[2][j].x, a3x = A[3][j].x;
            float a1y = A[1][j].y, a3y = A[3][j].y;
            float v0 = a0x + a1x + a2x + a3x;
            float v1 = a0x - a1y - a2x + a3y;
            float v2 = a0x - a1x + a2x - a3x;
            float v3 = a0x + a1y - a2x - a3y;
            op[(size_t)(n1      ) * WOUT + m] = v0 * sc;
            op[(size_t)(n1 + 32 ) * WOUT + m] = v1 * sc;
            op[(size_t)(n1 + 64 ) * WOUT + m] = v2 * sc;
            op[(size_t)(n1 + 96 ) * WOUT + m] = v3 * sc;
        }
    }
}

// ---------------- launch ----------------
extern "C" void kernel_launch(void* const* d_in, const int* in_sizes, int n_in,
                              void* d_out, int out_size) {
    (void)in_sizes; (void)n_in; (void)out_size;
    const float* x   = (const float*)d_in[0];
    const float* w1r = (const float*)d_in[1];
    const float* w1i = (const float*)d_in[2];
    const float* w2r = (const float*)d_in[3];
    const float* w2i = (const float*)d_in[4];
    float* out = (float*)d_out;

    k_fill<<<32, 256>>>();
    kW<<<SS * CI, 256>>>(w1r, w1i, w2r, w2i);        // 4096 blocks (weight transpose)
    kA<<<(BB * CI * HH) / 32, 256>>>(x);            // 8192 blocks
    kB<<<BB * CI, 256>>>();                          // 2048 blocks
    kC<<<SS * M2, 128>>>();                          // 2048 blocks
    kD<<<SS * 64, 272>>>();                          // 4096 blocks
    kE<<<BB * CO, 544>>>(out);                       // 2048 blocks
}